// round 8
// baseline (speedup 1.0000x reference)
#include <cuda_runtime.h>
#include <cuda_bf16.h>

// ---------------- problem constants ----------------
#define NV      50000      // nodes
#define NE      200000     // edges
#define NB      1024       // graphs
#define DD      24         // node feature dim
#define EF      8          // edge feature dim
#define EH      128        // edge MLP hidden
#define DW      576        // D*D
#define ME_PAD  200064     // 1563 * 128 (padded edge rows for GEMM)

// ---------------- device scratch (zero-init at module load) ----------------
__device__ float g_H[(size_t)ME_PAD * EH];      // 102 MB  relu(ea@W1+b1), pad rows stay 0
__device__ float g_We[(size_t)ME_PAD * DW];     // 461 MB  per-edge 24x24 weights
__device__ float g_agg[NV * DD];
__device__ float g_cnt[NV];
__device__ float g_x1[NV * DD];
__device__ float g_x2[NV * DD];
__device__ int   g_start[NB + 1];
__device__ float g_qstar[NB * 2 * DD];
__device__ float g_h[NB * DD];
__device__ float g_c[NB * DD];

// ---------------- zero kernels ----------------
__global__ void zero_all_kernel() {
    int i = blockIdx.x * blockDim.x + threadIdx.x;
    int stride = gridDim.x * blockDim.x;
    for (int k = i; k < NV * DD; k += stride) g_agg[k] = 0.f;
    for (int k = i; k < NV; k += stride) g_cnt[k] = 0.f;
    for (int k = i; k < NB * 2 * DD; k += stride) g_qstar[k] = 0.f;
    for (int k = i; k < NB * DD; k += stride) { g_h[k] = 0.f; g_c[k] = 0.f; }
}

__global__ void zero_agg_kernel() {
    int i = blockIdx.x * blockDim.x + threadIdx.x;
    int stride = gridDim.x * blockDim.x;
    for (int k = i; k < NV * DD; k += stride) g_agg[k] = 0.f;
}

// ---------------- stage A1: H = relu(edge_attr @ W1 + b1) ----------------
__global__ void __launch_bounds__(128) edge_mlp1_kernel(
    const float* __restrict__ ea, const float* __restrict__ w1,
    const float* __restrict__ b1)
{
    __shared__ float sw[EF * EH];
    __shared__ float sb[EH];
    __shared__ float sea[8 * EF];
    int t = threadIdx.x;
    for (int i = t; i < EF * EH; i += 128) sw[i] = w1[i];
    sb[t] = b1[t];
    int e0 = blockIdx.x * 8;
    for (int i = t; i < 8 * EF; i += 128) {
        int ee = e0 + i / EF;
        if (ee < NE) sea[i] = ea[(size_t)ee * EF + (i % EF)];
    }
    __syncthreads();
    #pragma unroll
    for (int q = 0; q < 8; q++) {
        int e = e0 + q;
        if (e >= NE) break;
        float acc = sb[t];
        #pragma unroll
        for (int i = 0; i < EF; i++) acc += sea[q * EF + i] * sw[i * EH + t];
        g_H[(size_t)e * EH + t] = fmaxf(acc, 0.f);
    }
}

// ---------------- stage A2: We = H @ W2 + b2  (fp32x2 packed GEMM) --------
// M=ME_PAD, K=128, N=576.  Block tile 128x64, 128 threads, 8x8 microtile.
__global__ void __launch_bounds__(128) gemm_we_kernel(
    const float* __restrict__ W2, const float* __restrict__ be2)
{
    __shared__ float As[16][132];   // [k][m], padded
    __shared__ float Bs[16][68];    // [k][n], padded (keeps 16B alignment)

    int t  = threadIdx.x;
    int bm = blockIdx.y, bn = blockIdx.x;
    int tx = t & 7;        // n-tile: 8 threads * 8 cols
    int ty = t >> 3;       // m-tile: 16 threads * 8 rows

    unsigned long long acc[8][4];
    #pragma unroll
    for (int i = 0; i < 8; i++)
        #pragma unroll
        for (int j = 0; j < 4; j++) acc[i][j] = 0ULL;

    const float* Ag = g_H + (size_t)bm * 128 * EH;
    const float* Bg = W2 + bn * 64;

    for (int kk = 0; kk < EH; kk += 16) {
        // load A tile (128x16) -> As transposed; 4 float4 per thread
        #pragma unroll
        for (int p = 0; p < 4; p++) {
            int g   = t + p * 128;
            int row = g >> 2;
            int kq  = (g & 3) * 4;
            float4 v = *reinterpret_cast<const float4*>(Ag + (size_t)row * EH + kk + kq);
            As[kq + 0][row] = v.x; As[kq + 1][row] = v.y;
            As[kq + 2][row] = v.z; As[kq + 3][row] = v.w;
        }
        // load B tile (16x64); 2 float4 per thread
        #pragma unroll
        for (int p = 0; p < 2; p++) {
            int g  = t + p * 128;
            int kr = g >> 4;
            int c4 = (g & 15) * 4;
            float4 v = *reinterpret_cast<const float4*>(Bg + (size_t)(kk + kr) * DW + c4);
            *reinterpret_cast<float4*>(&Bs[kr][c4]) = v;
        }
        __syncthreads();
        #pragma unroll
        for (int k = 0; k < 16; k++) {
            unsigned long long a2[8], b2[4];
            #pragma unroll
            for (int i = 0; i < 8; i++) {
                unsigned int au = __float_as_uint(As[k][ty * 8 + i]);
                asm("mov.b64 %0, {%1, %1};" : "=l"(a2[i]) : "r"(au));
            }
            #pragma unroll
            for (int j = 0; j < 4; j++)
                b2[j] = *reinterpret_cast<const unsigned long long*>(&Bs[k][tx * 8 + 2 * j]);
            #pragma unroll
            for (int i = 0; i < 8; i++)
                #pragma unroll
                for (int j = 0; j < 4; j++)
                    asm("fma.rn.f32x2 %0, %1, %2, %0;"
                        : "+l"(acc[i][j]) : "l"(a2[i]), "l"(b2[j]));
        }
        __syncthreads();
    }

    int ncol = bn * 64 + tx * 8;
    float bias[8];
    #pragma unroll
    for (int j = 0; j < 8; j++) bias[j] = be2[ncol + j];

    #pragma unroll
    for (int i = 0; i < 8; i++) {
        size_t row = (size_t)(bm * 128 + ty * 8 + i);
        float out[8];
        #pragma unroll
        for (int j = 0; j < 4; j++) {
            out[2 * j]     = __uint_as_float((unsigned int)(acc[i][j] & 0xffffffffULL)) + bias[2 * j];
            out[2 * j + 1] = __uint_as_float((unsigned int)(acc[i][j] >> 32)) + bias[2 * j + 1];
        }
        float4* dst = reinterpret_cast<float4*>(&g_We[row * DW + ncol]);
        dst[0] = make_float4(out[0], out[1], out[2], out[3]);
        dst[1] = make_float4(out[4], out[5], out[6], out[7]);
    }
}

// ---------------- graph boundaries from sorted batch (int32!) -------------
__global__ void graph_bounds_kernel(const int* __restrict__ batch) {
    int i = blockIdx.x * blockDim.x + threadIdx.x;
    if (i >= NV) return;
    int bi = batch[i];
    if (i == 0) {
        for (int g = 0; g <= bi; g++) g_start[g] = 0;
    } else {
        int bp = batch[i - 1];
        for (int g = bp + 1; g <= bi; g++) g_start[g] = i;
    }
    if (i == NV - 1) {
        for (int g = bi + 1; g <= NB; g++) g_start[g] = NV;
    }
}

// ---------------- message pass: agg[dst] += x[src] @ We[e]  (int32 idx) ---
__global__ void msg_pass_kernel(const float* __restrict__ x,
                                const int* __restrict__ ei, int addCnt)
{
    int w = (blockIdx.x * blockDim.x + threadIdx.x) >> 5;
    int lane = threadIdx.x & 31;
    if (w >= NE) return;
    int src = ei[w];
    int dst = ei[NE + w];
    float xv = (lane < DD) ? x[(size_t)src * DD + lane] : 0.f;
    float acc = 0.f;
    const float* We = g_We + (size_t)w * DW;
    #pragma unroll
    for (int i = 0; i < DD; i++) {
        float xi = __shfl_sync(0xffffffffu, xv, i);
        float wv = (lane < DD) ? We[i * DD + lane] : 0.f;
        acc += xi * wv;
    }
    if (lane < DD) atomicAdd(&g_agg[dst * DD + lane], acc);
    if (addCnt && lane == 0) atomicAdd(&g_cnt[dst], 1.f);
}

// ---------------- node update: agg/cnt + x@root + bias (opt relu) ---------
__global__ void node_update_kernel(const float* __restrict__ xin,
                                   const float* __restrict__ root,
                                   const float* __restrict__ bias,
                                   float* __restrict__ xout, int doRelu)
{
    int idx = blockIdx.x * blockDim.x + threadIdx.x;
    if (idx >= NV * DD) return;
    int v = idx / DD, j = idx % DD;
    float cnt = fmaxf(g_cnt[v], 1.f);
    float acc = g_agg[idx] / cnt + bias[j];
    const float* xr = xin + (size_t)v * DD;
    #pragma unroll
    for (int i = 0; i < DD; i++) acc += xr[i] * root[i * DD + j];
    if (doRelu) acc = fmaxf(acc, 0.f);
    xout[idx] = acc;
}

// ---------------- Set2Set: one full step (LSTM + attention) ---------------
__device__ __forceinline__ float sigm(float v) { return 1.f / (1.f + expf(-v)); }

__global__ void __launch_bounds__(128) s2s_step_kernel(
    const float* __restrict__ x2,
    const float* __restrict__ wih, const float* __restrict__ whh,
    const float* __restrict__ bih, const float* __restrict__ bhh)
{
    __shared__ float sq[2 * DD], shh[DD], scc[DD], sg[4 * DD], hn[DD];
    __shared__ float red[128];
    __shared__ float wr[4][DD];
    __shared__ float ws[4];

    int b = blockIdx.x, t = threadIdx.x;
    if (t < 2 * DD) sq[t] = g_qstar[b * 2 * DD + t];
    if (t < DD) { shh[t] = g_h[b * DD + t]; scc[t] = g_c[b * DD + t]; }
    __syncthreads();

    if (t < 4 * DD) {
        float g = bih[t] + bhh[t];
        #pragma unroll 8
        for (int u = 0; u < 2 * DD; u++) g += sq[u] * wih[t * 2 * DD + u];
        #pragma unroll 8
        for (int u = 0; u < DD; u++) g += shh[u] * whh[t * DD + u];
        sg[t] = g;
    }
    __syncthreads();

    if (t < DD) {
        float ig = sigm(sg[t]);
        float fg = sigm(sg[DD + t]);
        float gg = tanhf(sg[2 * DD + t]);
        float og = sigm(sg[3 * DD + t]);
        float cn = fg * scc[t] + ig * gg;
        float hv = og * tanhf(cn);
        g_c[b * DD + t] = cn;
        g_h[b * DD + t] = hv;
        hn[t] = hv;
    }
    __syncthreads();

    int s0 = g_start[b], s1 = g_start[b + 1];

    // pass 1: max of e = x . q
    float lmax = -3.4e38f;
    for (int n = s0 + t; n < s1; n += 128) {
        const float* xr = x2 + (size_t)n * DD;
        float e = 0.f;
        #pragma unroll
        for (int d = 0; d < DD; d++) e += xr[d] * hn[d];
        lmax = fmaxf(lmax, e);
    }
    red[t] = lmax;
    __syncthreads();
    for (int s = 64; s > 0; s >>= 1) {
        if (t < s) red[t] = fmaxf(red[t], red[t + s]);
        __syncthreads();
    }
    float emax = red[0];
    if (!(emax > -3.0e38f)) emax = 0.f;   // empty-graph guard (isfinite)

    // pass 2: softmax denom + weighted sum of x
    float lsum = 0.f;
    float lr[DD];
    #pragma unroll
    for (int d = 0; d < DD; d++) lr[d] = 0.f;
    for (int n = s0 + t; n < s1; n += 128) {
        const float* xr = x2 + (size_t)n * DD;
        float e = 0.f;
        #pragma unroll
        for (int d = 0; d < DD; d++) e += xr[d] * hn[d];
        float ex = expf(e - emax);
        lsum += ex;
        #pragma unroll
        for (int d = 0; d < DD; d++) lr[d] += ex * xr[d];
    }
    #pragma unroll
    for (int o = 16; o > 0; o >>= 1) {
        lsum += __shfl_xor_sync(0xffffffffu, lsum, o);
        #pragma unroll
        for (int d = 0; d < DD; d++) lr[d] += __shfl_xor_sync(0xffffffffu, lr[d], o);
    }
    int wid = t >> 5, lane = t & 31;
    if (lane == 0) ws[wid] = lsum;
    if (lane < DD) wr[wid][lane] = lr[lane];
    __syncthreads();

    if (t < DD) {
        float denom = ws[0] + ws[1] + ws[2] + ws[3];
        float rsum = wr[0][t] + wr[1][t] + wr[2][t] + wr[3][t];
        float r = rsum / fmaxf(denom, 1e-16f);
        g_qstar[b * 2 * DD + t] = hn[t];
        g_qstar[b * 2 * DD + DD + t] = r;
    }
}

// ---------------- heads: relu(q_star@W2+b)@W3+b ----------------
__global__ void heads_kernel(const float* __restrict__ wfc2, const float* __restrict__ bfc2,
                             const float* __restrict__ wfc3, const float* __restrict__ bfc3,
                             float* __restrict__ out)
{
    int b = blockIdx.x * blockDim.x + threadIdx.x;
    if (b >= NB) return;
    const float* q = g_qstar + b * 2 * DD;
    float hid[8];
    #pragma unroll
    for (int j = 0; j < 8; j++) {
        float h = bfc2[j];
        #pragma unroll 8
        for (int u = 0; u < 2 * DD; u++) h += q[u] * wfc2[u * 8 + j];
        hid[j] = fmaxf(h, 0.f);
    }
    #pragma unroll
    for (int k = 0; k < 2; k++) {
        float o = bfc3[k];
        #pragma unroll
        for (int j = 0; j < 8; j++) o += hid[j] * wfc3[j * 2 + k];
        out[b * 2 + k] = o;
    }
}

// ---------------- launch ----------------
extern "C" void kernel_launch(void* const* d_in, const int* in_sizes, int n_in,
                              void* d_out, int out_size)
{
    const float* x        = (const float*)d_in[0];
    const float* ea       = (const float*)d_in[1];
    const float* w_e1     = (const float*)d_in[2];
    const float* b_e1     = (const float*)d_in[3];
    const float* w_e2     = (const float*)d_in[4];
    const float* b_e2     = (const float*)d_in[5];
    const float* root     = (const float*)d_in[6];
    const float* bias_c   = (const float*)d_in[7];
    const float* w_ih     = (const float*)d_in[8];
    const float* w_hh     = (const float*)d_in[9];
    const float* b_ih     = (const float*)d_in[10];
    const float* b_hh     = (const float*)d_in[11];
    const float* w_fc2    = (const float*)d_in[12];
    const float* b_fc2    = (const float*)d_in[13];
    const float* w_fc3    = (const float*)d_in[14];
    const float* b_fc3    = (const float*)d_in[15];
    const int*   ei       = (const int*)d_in[16];   // JAX x64 off -> int32
    const int*   bat      = (const int*)d_in[17];   // JAX x64 off -> int32
    float* out            = (float*)d_out;

    // device-scratch addresses (host code runs only at capture time)
    float *px1 = nullptr, *px2 = nullptr;
    cudaGetSymbolAddress((void**)&px1, g_x1);
    cudaGetSymbolAddress((void**)&px2, g_x2);

    zero_all_kernel<<<1024, 256>>>();
    edge_mlp1_kernel<<<NE / 8, 128>>>(ea, w_e1, b_e1);
    {
        dim3 grid(DW / 64, ME_PAD / 128);   // 9 x 1563
        gemm_we_kernel<<<grid, 128>>>(w_e2, b_e2);
    }
    graph_bounds_kernel<<<(NV + 255) / 256, 256>>>(bat);

    // NNConv layer 1 (input x, output relu'd -> g_x1)
    msg_pass_kernel<<<NE / 8, 256>>>(x, ei, 1);
    node_update_kernel<<<(NV * DD + 255) / 256, 256>>>(x, root, bias_c, px1, 1);

    // NNConv layer 2 (input g_x1, output -> g_x2)
    zero_agg_kernel<<<512, 256>>>();
    msg_pass_kernel<<<NE / 8, 256>>>(px1, ei, 0);
    node_update_kernel<<<(NV * DD + 255) / 256, 256>>>(px1, root, bias_c, px2, 0);

    // Set2Set: 3 steps
    for (int s = 0; s < 3; s++)
        s2s_step_kernel<<<NB, 128>>>(px2, w_ih, w_hh, b_ih, b_hh);

    heads_kernel<<<(NB + 255) / 256, 256>>>(w_fc2, b_fc2, w_fc3, b_fc3, out);
}